// round 9
// baseline (speedup 1.0000x reference)
#include <cuda_runtime.h>
#include <cstdint>

#define L_SEQ   2048
#define D_HEAD  64
#define N_BH    64
#define BM      64
#define BN      64
#define N_ITERS 32
#define KS_STRIDE 68
#define OSM_STRIDE 66
#define SM_SCALE (1.0f/64.0f)
#define RES_ELEMS (N_BH * L_SEQ * D_HEAD)

#define TILE_FLOATS (BN * KS_STRIDE)            // 4352
#define PART_OFF (6 * TILE_FLOATS)
#define RINV_OFF (PART_OFF + 2 * BM)
#define SMEM_FLOATS (RINV_OFF + BM)
#define SMEM_BYTES (SMEM_FLOATS * 4)            // ~103 KB

__device__ float g_Vt[(size_t)N_BH * D_HEAD * L_SEQ];  // V^T, tf32-rounded
__device__ float g_Kc[(size_t)N_BH * L_SEQ * D_HEAD];  // K,   tf32-rounded

__device__ __forceinline__ float to_tf32(float x) {
    uint32_t u;
    asm("cvt.rna.tf32.f32 %0, %1;" : "=r"(u) : "f"(x));
    return __uint_as_float(u);
}

__device__ __forceinline__ void mma_tf32(float c[4], const float a[4], float b0, float b1) {
    asm volatile(
        "mma.sync.aligned.m16n8k8.row.col.f32.tf32.tf32.f32 "
        "{%0,%1,%2,%3}, {%4,%5,%6,%7}, {%8,%9}, {%0,%1,%2,%3};"
        : "+f"(c[0]), "+f"(c[1]), "+f"(c[2]), "+f"(c[3])
        : "r"(__float_as_uint(a[0])), "r"(__float_as_uint(a[1])),
          "r"(__float_as_uint(a[2])), "r"(__float_as_uint(a[3])),
          "r"(__float_as_uint(b0)),   "r"(__float_as_uint(b1)));
}

__device__ __forceinline__ void p_to_afrag(const float p[4], int lane, int t, float a[4]) {
    int src0 = (lane & ~3) | (t >> 1);
    int src1 = src0 | 2;
    float x0 = __shfl_sync(0xffffffffu, p[0], src0);
    float x1 = __shfl_sync(0xffffffffu, p[1], src0);
    float x2 = __shfl_sync(0xffffffffu, p[2], src0);
    float x3 = __shfl_sync(0xffffffffu, p[3], src0);
    float y0 = __shfl_sync(0xffffffffu, p[0], src1);
    float y1 = __shfl_sync(0xffffffffu, p[1], src1);
    float y2 = __shfl_sync(0xffffffffu, p[2], src1);
    float y3 = __shfl_sync(0xffffffffu, p[3], src1);
    bool odd = (t & 1);
    a[0] = to_tf32(odd ? x1 : x0);
    a[1] = to_tf32(odd ? x3 : x2);
    a[2] = to_tf32(odd ? y1 : y0);
    a[3] = to_tf32(odd ? y3 : y2);
}

__device__ __forceinline__ void cpa16(float* dst, const float* src) {
    uint32_t d = (uint32_t)__cvta_generic_to_shared(dst);
    asm volatile("cp.async.cg.shared.global [%0], [%1], 16;" :: "r"(d), "l"(src));
}
#define CP_COMMIT() asm volatile("cp.async.commit_group;")
#define CP_WAIT1()  asm volatile("cp.async.wait_group 1;")

__global__ void convert_k_kernel(const float* __restrict__ K) {
    size_t i = (size_t)blockIdx.x * blockDim.x + threadIdx.x;
    float4 v = ((const float4*)K)[i];
    v.x = to_tf32(v.x); v.y = to_tf32(v.y);
    v.z = to_tf32(v.z); v.w = to_tf32(v.w);
    ((float4*)g_Kc)[i] = v;
}

__global__ void transpose_v_kernel(const float* __restrict__ V) {
    __shared__ float tile[32][33];
    int bh = blockIdx.z;
    int s0 = blockIdx.x * 32, d0 = blockIdx.y * 32;
    const float* Vh = V + (size_t)bh * L_SEQ * D_HEAD;
    float* Vth = g_Vt + (size_t)bh * D_HEAD * L_SEQ;
    int x = threadIdx.x, y = threadIdx.y;
    #pragma unroll
    for (int j = 0; j < 32; j += 8)
        tile[y + j][x] = Vh[(size_t)(s0 + y + j) * D_HEAD + (d0 + x)];
    __syncthreads();
    #pragma unroll
    for (int j = 0; j < 32; j += 8)
        Vth[(size_t)(d0 + y + j) * L_SEQ + (s0 + x)] = to_tf32(tile[x][y + j]);
}

__device__ __forceinline__ void pf_k(float* buf, const float* Kh, int it, int tid) {
    const float* src = Kh + (size_t)it * BN * D_HEAD;
    #pragma unroll
    for (int i = tid; i < BN * 16; i += 256) {
        int r = i >> 4, c = i & 15;
        cpa16(buf + r * KS_STRIDE + c * 4, src + r * D_HEAD + c * 4);
    }
}
__device__ __forceinline__ void pf_v(float* buf, const float* Vth, int it, int tid) {
    #pragma unroll
    for (int i = tid; i < D_HEAD * 16; i += 256) {
        int d = i >> 4, c = i & 15;
        cpa16(buf + d * KS_STRIDE + c * 4, Vth + (size_t)d * L_SEQ + it * BN + c * 4);
    }
}

// QK: s[nf][r] += qa . K,  one 16-row m-group per warp
__device__ __forceinline__ void qk_mma(float s[4][4], const float qa[8][4],
                                       const float* Ks, int wn, int g, int t) {
    #pragma unroll
    for (int kf = 0; kf < 8; kf++)
        #pragma unroll
        for (int nf = 0; nf < 4; nf++) {
            int rn = wn * 32 + nf * 8 + g;
            float b0 = Ks[rn * KS_STRIDE + kf * 8 + t];
            float b1 = Ks[rn * KS_STRIDE + kf * 8 + t + 4];
            mma_tf32(s[nf], qa[kf], b0, b1);
        }
}

__global__ __launch_bounds__(256, 2)
void attn_kernel(const float* __restrict__ Q,
                 float* __restrict__ resOut, float* __restrict__ attOut) {
    extern __shared__ float smem[];
    float* bufK[3] = { smem, smem + TILE_FLOATS, smem + 2 * TILE_FLOATS };
    float* bufV[3] = { smem + 3 * TILE_FLOATS, smem + 4 * TILE_FLOATS, smem + 5 * TILE_FLOATS };
    float* partial = smem + PART_OFF;
    float* rinv    = smem + RINV_OFF;

    const int tid  = threadIdx.x;
    const int lane = tid & 31;
    const int wid  = tid >> 5;
    const int wm   = wid >> 1;     // 0..3 : 16-row group
    const int wn   = wid & 1;      // 0..1 : 32-col seq slice
    const int g    = lane >> 2;
    const int t    = lane & 3;
    const int bh   = blockIdx.y;
    const int m0   = blockIdx.x * BM;

    const float* Qh  = Q    + ((size_t)bh * L_SEQ + m0) * D_HEAD;
    const float* Kh  = g_Kc + (size_t)bh * L_SEQ * D_HEAD;
    const float* Vth = g_Vt + (size_t)bh * D_HEAD * L_SEQ;
    float*       attH = attOut + (size_t)bh * L_SEQ * L_SEQ;

    // Q fragments (16 rows per warp), register-resident
    float qa[8][4];
    {
        int r0 = wm * 16 + g;
        #pragma unroll
        for (int kf = 0; kf < 8; kf++) {
            qa[kf][0] = to_tf32(Qh[r0 * D_HEAD + kf * 8 + t]);
            qa[kf][1] = to_tf32(Qh[(r0 + 8) * D_HEAD + kf * 8 + t]);
            qa[kf][2] = to_tf32(Qh[r0 * D_HEAD + kf * 8 + t + 4]);
            qa[kf][3] = to_tf32(Qh[(r0 + 8) * D_HEAD + kf * 8 + t + 4]);
        }
    }

    float rs[2] = {0.f, 0.f};

    // ================= pass 1: row sums of exp(s/64) =================
    pf_k(bufK[0], Kh, 0, tid); CP_COMMIT();
    pf_k(bufK[1], Kh, 1, tid); CP_COMMIT();
    for (int it = 0; it < N_ITERS; it++) {
        CP_WAIT1();
        __syncthreads();
        if (it + 2 < N_ITERS) pf_k(bufK[(it + 2) % 3], Kh, it + 2, tid);
        CP_COMMIT();

        float s[4][4];
        #pragma unroll
        for (int nf = 0; nf < 4; nf++)
            #pragma unroll
            for (int r = 0; r < 4; r++) s[nf][r] = 0.f;

        qk_mma(s, qa, bufK[it % 3], wn, g, t);

        #pragma unroll
        for (int nf = 0; nf < 4; nf++) {
            rs[0] += __expf(s[nf][0] * SM_SCALE) + __expf(s[nf][1] * SM_SCALE);
            rs[1] += __expf(s[nf][2] * SM_SCALE) + __expf(s[nf][3] * SM_SCALE);
        }
    }

    #pragma unroll
    for (int h = 0; h < 2; h++) {
        rs[h] += __shfl_xor_sync(0xffffffffu, rs[h], 1);
        rs[h] += __shfl_xor_sync(0xffffffffu, rs[h], 2);
    }
    if (t == 0) {
        int r = wm * 16 + g;
        partial[wn * BM + r]     = rs[0];
        partial[wn * BM + r + 8] = rs[1];
    }
    __syncthreads();
    if (tid < BM) rinv[tid] = 1.0f / (partial[tid] + partial[BM + tid]);
    __syncthreads();

    float inv[2];
    inv[0] = rinv[wm * 16 + g];
    inv[1] = rinv[wm * 16 + g + 8];

    float o[8][4];
    #pragma unroll
    for (int nf = 0; nf < 8; nf++)
        #pragma unroll
        for (int r = 0; r < 4; r++) o[nf][r] = 0.f;

    // ================= pass 2: att write + P@V =================
    pf_k(bufK[0], Kh, 0, tid); pf_v(bufV[0], Vth, 0, tid); CP_COMMIT();
    pf_k(bufK[1], Kh, 1, tid); pf_v(bufV[1], Vth, 1, tid); CP_COMMIT();
    for (int it = 0; it < N_ITERS; it++) {
        CP_WAIT1();
        __syncthreads();
        if (it + 2 < N_ITERS) { pf_k(bufK[(it + 2) % 3], Kh, it + 2, tid);
                                pf_v(bufV[(it + 2) % 3], Vth, it + 2, tid); }
        CP_COMMIT();

        const float* Ks  = bufK[it % 3];
        const float* Vts = bufV[it % 3];

        float s[4][4];
        #pragma unroll
        for (int nf = 0; nf < 4; nf++)
            #pragma unroll
            for (int r = 0; r < 4; r++) s[nf][r] = 0.f;

        qk_mma(s, qa, Ks, wn, g, t);

        #pragma unroll
        for (int nf = 0; nf < 4; nf++) {
            float p0 = __expf(s[nf][0] * SM_SCALE) * inv[0];
            float p1 = __expf(s[nf][1] * SM_SCALE) * inv[0];
            float p2 = __expf(s[nf][2] * SM_SCALE) * inv[1];
            float p3 = __expf(s[nf][3] * SM_SCALE) * inv[1];
            s[nf][0] = p0; s[nf][1] = p1;
            s[nf][2] = p2; s[nf][3] = p3;
            size_t row = (size_t)(m0 + wm * 16 + g);
            int col = it * BN + wn * 32 + nf * 8 + 2 * t;
            *(float2*)&attH[row * L_SEQ + col]       = make_float2(p0, p1);
            *(float2*)&attH[(row + 8) * L_SEQ + col] = make_float2(p2, p3);
        }

        #pragma unroll
        for (int kc = 0; kc < 4; kc++) {
            float a[4];
            p_to_afrag(s[kc], lane, t, a);
            #pragma unroll
            for (int nf = 0; nf < 8; nf++) {
                int rd = nf * 8 + g;
                float b0 = Vts[rd * KS_STRIDE + wn * 32 + kc * 8 + t];
                float b1 = Vts[rd * KS_STRIDE + wn * 32 + kc * 8 + t + 4];
                mma_tf32(o[nf], a, b0, b1);
            }
        }
    }

    // reduce split-k partials across the wn pair, write res
    __syncthreads();
    float* osm = smem;
    if (wn == 1) {
        #pragma unroll
        for (int nf = 0; nf < 8; nf++) {
            int r = wm * 16 + g;
            int c = nf * 8 + 2 * t;
            *(float2*)&osm[r * OSM_STRIDE + c]       = make_float2(o[nf][0], o[nf][1]);
            *(float2*)&osm[(r + 8) * OSM_STRIDE + c] = make_float2(o[nf][2], o[nf][3]);
        }
    }
    __syncthreads();
    if (wn == 0) {
        float* resH = resOut + ((size_t)bh * L_SEQ + m0) * D_HEAD;
        #pragma unroll
        for (int nf = 0; nf < 8; nf++) {
            int r = wm * 16 + g;
            int c = nf * 8 + 2 * t;
            float2 u0 = *(float2*)&osm[r * OSM_STRIDE + c];
            float2 u1 = *(float2*)&osm[(r + 8) * OSM_STRIDE + c];
            *(float2*)&resH[(size_t)r * D_HEAD + c] =
                make_float2(o[nf][0] + u0.x, o[nf][1] + u0.y);
            *(float2*)&resH[(size_t)(r + 8) * D_HEAD + c] =
                make_float2(o[nf][2] + u1.x, o[nf][3] + u1.y);
        }
    }
}

extern "C" void kernel_launch(void* const* d_in, const int* in_sizes, int n_in,
                              void* d_out, int out_size) {
    const float* Q = (const float*)d_in[0];
    const float* K = (const float*)d_in[1];
    const float* V = (const float*)d_in[2];
    float* res = (float*)d_out;
    float* att = (float*)d_out + RES_ELEMS;

    cudaFuncSetAttribute(attn_kernel, cudaFuncAttributeMaxDynamicSharedMemorySize, SMEM_BYTES);

    convert_k_kernel<<<(N_BH * L_SEQ * D_HEAD / 4) / 256, 256>>>(K);
    transpose_v_kernel<<<dim3(L_SEQ / 32, D_HEAD / 32, N_BH), dim3(32, 8)>>>(V);
    attn_kernel<<<dim3(L_SEQ / BM, N_BH), 256, SMEM_BYTES>>>(Q, res, att);
}

// round 11
// speedup vs baseline: 1.3971x; 1.3971x over previous
#include <cuda_runtime.h>
#include <cuda_bf16.h>
#include <cstdint>

#define L_SEQ   2048
#define D_HEAD  64
#define N_BH    64
#define BM      128
#define BN      64
#define N_ITERS 32
#define VS_STRIDE 68            // floats, V tile row stride
#define OSM_STRIDE 66
#define SM_SCALE (1.0f/64.0f)
#define RES_ELEMS (N_BH * L_SEQ * D_HEAD)

// byte layout in dynamic smem
#define KB_TILE_B 9216          // 64 rows * 144 B (bf16, stride 72 elems)
#define V_TILE_B  17408         // 64 rows * 272 B (f32, stride 68)
#define KB0_OFF   0
#define V0_OFF    (3 * KB_TILE_B)                 // 27648
#define PART_OFF  (V0_OFF + 3 * V_TILE_B)         // 79872
#define RINV_OFF  (PART_OFF + 2 * BM * 4)         // 80896
#define SMEM_BYTES (RINV_OFF + BM * 4)            // 81408

__device__ float          g_Vt[(size_t)N_BH * D_HEAD * L_SEQ];   // V^T, tf32-rounded
__device__ __nv_bfloat16  g_Kb[(size_t)N_BH * L_SEQ * D_HEAD];   // K in bf16

__device__ __forceinline__ float to_tf32(float x) {
    uint32_t u;
    asm("cvt.rna.tf32.f32 %0, %1;" : "=r"(u) : "f"(x));
    return __uint_as_float(u);
}

__device__ __forceinline__ uint32_t pk_bf16(float lo, float hi) {
    __nv_bfloat16 l = __float2bfloat16(lo), h = __float2bfloat16(hi);
    return ((uint32_t)__bfloat16_as_ushort(h) << 16) | __bfloat16_as_ushort(l);
}

// bf16 m16n8k16: a[4], b[2], c[4]
__device__ __forceinline__ void mma_bf16(float c[4], const uint32_t a[4],
                                         uint32_t b0, uint32_t b1) {
    asm volatile(
        "mma.sync.aligned.m16n8k16.row.col.f32.bf16.bf16.f32 "
        "{%0,%1,%2,%3}, {%4,%5,%6,%7}, {%8,%9}, {%0,%1,%2,%3};"
        : "+f"(c[0]), "+f"(c[1]), "+f"(c[2]), "+f"(c[3])
        : "r"(a[0]), "r"(a[1]), "r"(a[2]), "r"(a[3]), "r"(b0), "r"(b1));
}

// tf32 m16n8k8 for PV (res precision)
__device__ __forceinline__ void mma_tf32(float c[4], const float a[4], float b0, float b1) {
    asm volatile(
        "mma.sync.aligned.m16n8k8.row.col.f32.tf32.tf32.f32 "
        "{%0,%1,%2,%3}, {%4,%5,%6,%7}, {%8,%9}, {%0,%1,%2,%3};"
        : "+f"(c[0]), "+f"(c[1]), "+f"(c[2]), "+f"(c[3])
        : "r"(__float_as_uint(a[0])), "r"(__float_as_uint(a[1])),
          "r"(__float_as_uint(a[2])), "r"(__float_as_uint(a[3])),
          "r"(__float_as_uint(b0)),   "r"(__float_as_uint(b1)));
}

__device__ __forceinline__ void p_to_afrag(const float p[4], int lane, int t, float a[4]) {
    int src0 = (lane & ~3) | (t >> 1);
    int src1 = src0 | 2;
    float x0 = __shfl_sync(0xffffffffu, p[0], src0);
    float x1 = __shfl_sync(0xffffffffu, p[1], src0);
    float x2 = __shfl_sync(0xffffffffu, p[2], src0);
    float x3 = __shfl_sync(0xffffffffu, p[3], src0);
    float y0 = __shfl_sync(0xffffffffu, p[0], src1);
    float y1 = __shfl_sync(0xffffffffu, p[1], src1);
    float y2 = __shfl_sync(0xffffffffu, p[2], src1);
    float y3 = __shfl_sync(0xffffffffu, p[3], src1);
    bool odd = (t & 1);
    a[0] = to_tf32(odd ? x1 : x0);
    a[1] = to_tf32(odd ? x3 : x2);
    a[2] = to_tf32(odd ? y1 : y0);
    a[3] = to_tf32(odd ? y3 : y2);
}

__device__ __forceinline__ void cpa16(void* dst, const void* src) {
    uint32_t d = (uint32_t)__cvta_generic_to_shared(dst);
    asm volatile("cp.async.cg.shared.global [%0], [%1], 16;" :: "r"(d), "l"(src));
}
#define CP_COMMIT() asm volatile("cp.async.commit_group;")
#define CP_WAIT1()  asm volatile("cp.async.wait_group 1;")

__global__ void convert_k_kernel(const float* __restrict__ K) {
    size_t i = (size_t)blockIdx.x * blockDim.x + threadIdx.x;   // 4 floats each
    float4 v = ((const float4*)K)[i];
    uint2 o;
    o.x = pk_bf16(v.x, v.y);
    o.y = pk_bf16(v.z, v.w);
    ((uint2*)g_Kb)[i] = o;
}

__global__ void transpose_v_kernel(const float* __restrict__ V) {
    __shared__ float tile[32][33];
    int bh = blockIdx.z;
    int s0 = blockIdx.x * 32, d0 = blockIdx.y * 32;
    const float* Vh = V + (size_t)bh * L_SEQ * D_HEAD;
    float* Vth = g_Vt + (size_t)bh * D_HEAD * L_SEQ;
    int x = threadIdx.x, y = threadIdx.y;
    #pragma unroll
    for (int j = 0; j < 32; j += 8)
        tile[y + j][x] = Vh[(size_t)(s0 + y + j) * D_HEAD + (d0 + x)];
    __syncthreads();
    #pragma unroll
    for (int j = 0; j < 32; j += 8)
        Vth[(size_t)(d0 + y + j) * L_SEQ + (s0 + x)] = to_tf32(tile[x][y + j]);
}

// K tile: 64 rows x 128B (bf16), dst stride 144B
__device__ __forceinline__ void pf_k(char* buf, const __nv_bfloat16* Kh, int it, int tid) {
    const char* src = (const char*)(Kh + (size_t)it * BN * D_HEAD);
    #pragma unroll
    for (int i = tid; i < BN * 8; i += 256) {
        int r = i >> 3, c = i & 7;
        cpa16(buf + r * 144 + c * 16, src + r * 128 + c * 16);
    }
}
// V tile: 64 d-rows x 256B (f32), dst stride 272B
__device__ __forceinline__ void pf_v(char* buf, const float* Vth, int it, int tid) {
    #pragma unroll
    for (int i = tid; i < D_HEAD * 16; i += 256) {
        int d = i >> 4, c = i & 15;
        cpa16(buf + d * 272 + c * 16, Vth + (size_t)d * L_SEQ + it * BN + c * 4);
    }
}

// QK bf16: s[mf][nf][r] += Q . K^T over k=64 (4 x k16)
__device__ __forceinline__ void qk_mma(float s[2][4][4], const uint32_t qa[2][4][4],
                                       const char* KsB, int wn, int g, int t) {
    #pragma unroll
    for (int kf = 0; kf < 4; kf++)
        #pragma unroll
        for (int nf = 0; nf < 4; nf++) {
            int rn = wn * 32 + nf * 8 + g;
            const char* base = KsB + rn * 144 + kf * 32 + 4 * t;
            uint32_t b0 = *(const uint32_t*)base;
            uint32_t b1 = *(const uint32_t*)(base + 16);
            mma_bf16(s[0][nf], qa[0][kf], b0, b1);
            mma_bf16(s[1][nf], qa[1][kf], b0, b1);
        }
}

__global__ __launch_bounds__(256, 1)
void attn_kernel(const float* __restrict__ Q,
                 float* __restrict__ resOut, float* __restrict__ attOut) {
    extern __shared__ char smc[];
    char* bufK[3] = { smc, smc + KB_TILE_B, smc + 2 * KB_TILE_B };
    char* bufV[3] = { smc + V0_OFF, smc + V0_OFF + V_TILE_B, smc + V0_OFF + 2 * V_TILE_B };
    float* partial = (float*)(smc + PART_OFF);
    float* rinv    = (float*)(smc + RINV_OFF);

    const int tid  = threadIdx.x;
    const int lane = tid & 31;
    const int wid  = tid >> 5;
    const int wm   = wid >> 1;     // 0..3 : 32-row group
    const int wn   = wid & 1;      // 0..1 : 32-col seq slice
    const int g    = lane >> 2;
    const int t    = lane & 3;
    const int bh   = blockIdx.y;
    const int m0   = blockIdx.x * BM;

    const float*         Qh  = Q    + ((size_t)bh * L_SEQ + m0) * D_HEAD;
    const __nv_bfloat16* Kh  = g_Kb + (size_t)bh * L_SEQ * D_HEAD;
    const float*         Vth = g_Vt + (size_t)bh * D_HEAD * L_SEQ;
    float*               attH = attOut + (size_t)bh * L_SEQ * L_SEQ;

    // Q bf16 A-fragments (m16k16), register-resident
    uint32_t qa[2][4][4];
    #pragma unroll
    for (int mf = 0; mf < 2; mf++) {
        int r0 = wm * 32 + mf * 16 + g;
        #pragma unroll
        for (int kf = 0; kf < 4; kf++) {
            int c = kf * 16 + 2 * t;
            qa[mf][kf][0] = pk_bf16(Qh[r0 * D_HEAD + c],           Qh[r0 * D_HEAD + c + 1]);
            qa[mf][kf][1] = pk_bf16(Qh[(r0 + 8) * D_HEAD + c],     Qh[(r0 + 8) * D_HEAD + c + 1]);
            qa[mf][kf][2] = pk_bf16(Qh[r0 * D_HEAD + c + 8],       Qh[r0 * D_HEAD + c + 9]);
            qa[mf][kf][3] = pk_bf16(Qh[(r0 + 8) * D_HEAD + c + 8], Qh[(r0 + 8) * D_HEAD + c + 9]);
        }
    }

    float rs[2][2] = {{0.f, 0.f}, {0.f, 0.f}};

    // ================= pass 1: row sums of exp(s/64) =================
    pf_k(bufK[0], Kh, 0, tid); CP_COMMIT();
    pf_k(bufK[1], Kh, 1, tid); CP_COMMIT();
    for (int it = 0; it < N_ITERS; it++) {
        CP_WAIT1();
        __syncthreads();
        if (it + 2 < N_ITERS) pf_k(bufK[(it + 2) % 3], Kh, it + 2, tid);
        CP_COMMIT();

        float s[2][4][4];
        #pragma unroll
        for (int mf = 0; mf < 2; mf++)
            #pragma unroll
            for (int nf = 0; nf < 4; nf++)
                #pragma unroll
                for (int r = 0; r < 4; r++) s[mf][nf][r] = 0.f;

        qk_mma(s, qa, bufK[it % 3], wn, g, t);

        #pragma unroll
        for (int mf = 0; mf < 2; mf++)
            #pragma unroll
            for (int nf = 0; nf < 4; nf++) {
                rs[mf][0] += __expf(s[mf][nf][0] * SM_SCALE) + __expf(s[mf][nf][1] * SM_SCALE);
                rs[mf][1] += __expf(s[mf][nf][2] * SM_SCALE) + __expf(s[mf][nf][3] * SM_SCALE);
            }
    }

    #pragma unroll
    for (int mf = 0; mf < 2; mf++) {
        #pragma unroll
        for (int h = 0; h < 2; h++) {
            rs[mf][h] += __shfl_xor_sync(0xffffffffu, rs[mf][h], 1);
            rs[mf][h] += __shfl_xor_sync(0xffffffffu, rs[mf][h], 2);
        }
        if (t == 0) {
            int r = wm * 32 + mf * 16 + g;
            partial[wn * BM + r]     = rs[mf][0];
            partial[wn * BM + r + 8] = rs[mf][1];
        }
    }
    __syncthreads();
    if (tid < BM) rinv[tid] = 1.0f / (partial[tid] + partial[BM + tid]);
    __syncthreads();

    float inv[2][2];
    #pragma unroll
    for (int mf = 0; mf < 2; mf++) {
        inv[mf][0] = rinv[wm * 32 + mf * 16 + g];
        inv[mf][1] = rinv[wm * 32 + mf * 16 + g + 8];
    }

    float o[2][8][4];
    #pragma unroll
    for (int mf = 0; mf < 2; mf++)
        #pragma unroll
        for (int nf = 0; nf < 8; nf++)
            #pragma unroll
            for (int r = 0; r < 4; r++) o[mf][nf][r] = 0.f;

    // ================= pass 2: att write + P@V =================
    pf_k(bufK[0], Kh, 0, tid); pf_v(bufV[0], Vth, 0, tid); CP_COMMIT();
    pf_k(bufK[1], Kh, 1, tid); pf_v(bufV[1], Vth, 1, tid); CP_COMMIT();
    for (int it = 0; it < N_ITERS; it++) {
        CP_WAIT1();
        __syncthreads();
        if (it + 2 < N_ITERS) { pf_k(bufK[(it + 2) % 3], Kh, it + 2, tid);
                                pf_v(bufV[(it + 2) % 3], Vth, it + 2, tid); }
        CP_COMMIT();

        const char*  KsB = bufK[it % 3];
        const float* Vts = (const float*)bufV[it % 3];

        float s[2][4][4];
        #pragma unroll
        for (int mf = 0; mf < 2; mf++)
            #pragma unroll
            for (int nf = 0; nf < 4; nf++)
                #pragma unroll
                for (int r = 0; r < 4; r++) s[mf][nf][r] = 0.f;

        qk_mma(s, qa, KsB, wn, g, t);

        #pragma unroll
        for (int mf = 0; mf < 2; mf++)
            #pragma unroll
            for (int nf = 0; nf < 4; nf++) {
                float p0 = __expf(s[mf][nf][0] * SM_SCALE) * inv[mf][0];
                float p1 = __expf(s[mf][nf][1] * SM_SCALE) * inv[mf][0];
                float p2 = __expf(s[mf][nf][2] * SM_SCALE) * inv[mf][1];
                float p3 = __expf(s[mf][nf][3] * SM_SCALE) * inv[mf][1];
                s[mf][nf][0] = p0; s[mf][nf][1] = p1;
                s[mf][nf][2] = p2; s[mf][nf][3] = p3;
                size_t row = (size_t)(m0 + wm * 32 + mf * 16 + g);
                int col = it * BN + wn * 32 + nf * 8 + 2 * t;
                *(float2*)&attH[row * L_SEQ + col]       = make_float2(p0, p1);
                *(float2*)&attH[(row + 8) * L_SEQ + col] = make_float2(p2, p3);
            }

        #pragma unroll
        for (int kc = 0; kc < 4; kc++)
            #pragma unroll
            for (int mf = 0; mf < 2; mf++) {
                float a[4];
                p_to_afrag(s[mf][kc], lane, t, a);
                #pragma unroll
                for (int nf = 0; nf < 8; nf++) {
                    int rd = nf * 8 + g;
                    float b0 = Vts[rd * VS_STRIDE + wn * 32 + kc * 8 + t];
                    float b1 = Vts[rd * VS_STRIDE + wn * 32 + kc * 8 + t + 4];
                    mma_tf32(o[mf][nf], a, b0, b1);
                }
            }
    }

    // reduce split-k partials across the wn pair, write res
    __syncthreads();
    float* osm = (float*)smc;
    if (wn == 1) {
        #pragma unroll
        for (int mf = 0; mf < 2; mf++)
            #pragma unroll
            for (int nf = 0; nf < 8; nf++) {
                int r = wm * 32 + mf * 16 + g;
                int c = nf * 8 + 2 * t;
                *(float2*)&osm[r * OSM_STRIDE + c]       = make_float2(o[mf][nf][0], o[mf][nf][1]);
                *(float2*)&osm[(r + 8) * OSM_STRIDE + c] = make_float2(o[mf][nf][2], o[mf][nf][3]);
            }
    }
    __syncthreads();
    if (wn == 0) {
        float* resH = resOut + ((size_t)bh * L_SEQ + m0) * D_HEAD;
        #pragma unroll
        for (int mf = 0; mf < 2; mf++)
            #pragma unroll
            for (int nf = 0; nf < 8; nf++) {
                int r = wm * 32 + mf * 16 + g;
                int c = nf * 8 + 2 * t;
                float2 u0 = *(float2*)&osm[r * OSM_STRIDE + c];
                float2 u1 = *(float2*)&osm[(r + 8) * OSM_STRIDE + c];
                *(float2*)&resH[(size_t)r * D_HEAD + c] =
                    make_float2(o[mf][nf][0] + u0.x, o[mf][nf][1] + u0.y);
                *(float2*)&resH[(size_t)(r + 8) * D_HEAD + c] =
                    make_float2(o[mf][nf][2] + u1.x, o[mf][nf][3] + u1.y);
            }
    }
}

extern "C" void kernel_launch(void* const* d_in, const int* in_sizes, int n_in,
                              void* d_out, int out_size) {
    const float* Q = (const float*)d_in[0];
    const float* K = (const float*)d_in[1];
    const float* V = (const float*)d_in[2];
    float* res = (float*)d_out;
    float* att = (float*)d_out + RES_ELEMS;

    cudaFuncSetAttribute(attn_kernel, cudaFuncAttributeMaxDynamicSharedMemorySize, SMEM_BYTES);

    convert_k_kernel<<<(N_BH * L_SEQ * D_HEAD / 4) / 256, 256>>>(K);
    transpose_v_kernel<<<dim3(L_SEQ / 32, D_HEAD / 32, N_BH), dim3(32, 8)>>>(V);
    attn_kernel<<<dim3(L_SEQ / BM, N_BH), 256, SMEM_BYTES>>>(Q, res, att);
}